// round 11
// baseline (speedup 1.0000x reference)
#include <cuda_runtime.h>
#include <cuda_fp16.h>
#include <cstdint>

#define N_ROWS 8192
#define IN_F   2048
#define OUT_F  2048
#define XN     512
#define NPROD  8

static constexpr size_t NT = (size_t)N_ROWS * XN;

// ---------------- static device scratch ----------------
__device__ __half g_xc[NPROD * NT];          // 8 X-combos [8192 x 512] fp16
__device__ __half g_wt[NPROD * XN * XN];     // 8 W-combos [512 x 512] fp16, [nu][kappa]

// ---------------- prep: X combos ----------------
__global__ void make_xc_kernel(const float* __restrict__ in) {
    size_t idx = (size_t)blockIdx.x * blockDim.x + threadIdx.x;
    if (idx >= NT) return;
    float4 v = reinterpret_cast<const float4*>(in)[idx];  // (X0,X1,X2,X3)
    g_xc[0 * NT + idx] = __float2half_rn(v.x + v.y);
    g_xc[1 * NT + idx] = __float2half_rn(v.z - v.w);
    g_xc[2 * NT + idx] = __float2half_rn(v.z + v.w);
    g_xc[3 * NT + idx] = __float2half_rn(v.x - v.y);
    g_xc[4 * NT + idx] = __float2half_rn(v.y + v.z);
    g_xc[5 * NT + idx] = __float2half_rn(v.y - v.z);
    g_xc[6 * NT + idx] = __float2half_rn(v.x - v.w);
    g_xc[7 * NT + idx] = __float2half_rn(v.x + v.w);
}

// ---------------- prep: W combos (transposed to [nu][kappa]) ----------------
__global__ void make_wc_kernel(const float* __restrict__ w) {
    __shared__ __half tile[NPROD][32][33];
    const int kap0 = blockIdx.x * 32;
    const int nu0  = blockIdx.y * 32;
    const int tid = threadIdx.x;
    for (int p = 0; p < 4; ++p) {
        int r = p * 8 + (tid >> 5);
        int cnu = tid & 31;
        const float* wr = w + (size_t)(kap0 + r) * OUT_F + nu0 + cnu;
        float b0 = wr[0], b1 = wr[512], b2 = wr[1024], b3 = wr[1536];
        tile[0][r][cnu] = __float2half_rn(b0 - b1);
        tile[1][r][cnu] = __float2half_rn(b2 - b3);
        tile[2][r][cnu] = __float2half_rn(b0 + b1);
        tile[3][r][cnu] = __float2half_rn(b2 + b3);
        tile[4][r][cnu] = __float2half_rn(0.5f * (b1 + b3));
        tile[5][r][cnu] = __float2half_rn(0.5f * (b1 - b3));
        tile[6][r][cnu] = __float2half_rn(0.5f * (b0 - b2));
        tile[7][r][cnu] = __float2half_rn(0.5f * (b0 + b2));
    }
    __syncthreads();
    for (int p = 0; p < 4; ++p) {
        int rnu = p * 8 + (tid >> 5);
        int ck  = tid & 31;
#pragma unroll
        for (int i = 0; i < NPROD; ++i) {
            g_wt[(size_t)i * XN * XN + (size_t)(nu0 + rnu) * XN + kap0 + ck] = tile[i][ck][rnu];
        }
    }
}

// ---------------- PTX helpers ----------------
__device__ __forceinline__ uint32_t smem_u32(const void* p) {
    uint32_t a;
    asm("{ .reg .u64 t; cvta.to.shared.u64 t, %1; cvt.u32.u64 %0, t; }" : "=r"(a) : "l"(p));
    return a;
}

#define CP_ASYNC16(dst, src) \
    asm volatile("cp.async.cg.shared.global [%0], [%1], 16;" :: "r"(dst), "l"(src))
#define CP_COMMIT() asm volatile("cp.async.commit_group;")
#define CP_WAIT(n)  asm volatile("cp.async.wait_group %0;" :: "n"(n))

__device__ __forceinline__ void ldsm_x4(uint32_t& r0, uint32_t& r1, uint32_t& r2, uint32_t& r3,
                                        uint32_t addr) {
    asm volatile("ldmatrix.sync.aligned.m8n8.x4.shared.b16 {%0,%1,%2,%3}, [%4];"
                 : "=r"(r0), "=r"(r1), "=r"(r2), "=r"(r3) : "r"(addr));
}

__device__ __forceinline__ void hmma(float* c, const uint32_t* a, uint32_t b0, uint32_t b1) {
    asm volatile(
        "mma.sync.aligned.m16n8k16.row.col.f32.f16.f16.f32 "
        "{%0,%1,%2,%3}, {%4,%5,%6,%7}, {%8,%9}, {%0,%1,%2,%3};"
        : "+f"(c[0]), "+f"(c[1]), "+f"(c[2]), "+f"(c[3])
        : "r"(a[0]), "r"(a[1]), "r"(a[2]), "r"(a[3]), "r"(b0), "r"(b1));
}

// ---------------- fused GEMM+combine ----------------
// CTA: 128 m x 64 nu. Loops z=0..7 internally; folds T_z into 4 output accs.
#define BM 128
#define BNU 64
#define BK 64
#define STAGES 4
#define THREADS 256

static constexpr int A_CHUNK_B = BM * 32 * 2;    // 8192 B (128 rows x 32k)
static constexpr int B_CHUNK_B = BNU * 32 * 2;   // 4096 B (64 rows x 32k)
static constexpr int A_OP_B = 2 * A_CHUNK_B;     // 16 KB
static constexpr int STAGE_B = A_OP_B + 2 * B_CHUNK_B;  // 24 KB
static constexpr int SMEM_TOTAL = STAGES * STAGE_B;     // 96 KB
static constexpr int TOTAL_IT = NPROD * (XN / BK);      // 64

// sign of T_z's contribution to output component b
__device__ __constant__ signed char SG[8][4] = {
    { 0, +1,  0,  0},   // T0 -> O1
    {+1,  0,  0,  0},   // T1 -> O0
    { 0,  0, +1,  0},   // T2 -> O2
    { 0,  0,  0, -1},   // T3 -> -O3
    {+1, +1, -1, -1},   // T4
    {+1, +1, +1, +1},   // T5
    {+1, -1, +1, -1},   // T6
    {+1, -1, -1, +1},   // T7
};

__global__ void __launch_bounds__(THREADS, 1) qfused_gemm(
    const float* __restrict__ bias, float* __restrict__ out)
{
    extern __shared__ char smem[];
    const uint32_t sbase = smem_u32(smem);
    const int tid  = threadIdx.x;
    const int wid  = tid >> 5;
    const int lane = tid & 31;
    const int warp_m = wid & 3;    // 4 warps x 32 rows
    const int warp_n = wid >> 2;   // 2 warps x 32 nu
    const int m0 = blockIdx.y * BM;
    const int n0 = blockIdx.x * BNU;

    const int lr = tid >> 2;             // row 0..63
    const int lc = tid & 3;              // 16B chunk col
    const uint32_t dst_off = lr * 64 + ((lc ^ ((lr >> 1) & 3)) << 4);
    const size_t src_off = (size_t)lr * XN + lc * 8;

    // ldmatrix lane addressing
    const int g = lane >> 3, r = lane & 7;
    uint32_t a_row[2], a_sw[2];
    const int a_gbit = g >> 1;
#pragma unroll
    for (int mt = 0; mt < 2; ++mt) {
        int row = warp_m * 32 + mt * 16 + (g & 1) * 8 + r;
        a_row[mt] = row * 64;
        a_sw[mt]  = (row >> 1) & 3;
    }
    uint32_t b_row[2], b_sw[2];
    const int b_gbit = g & 1;
#pragma unroll
    for (int np = 0; np < 2; ++np) {
        int row = warp_n * 32 + np * 16 + (g >> 1) * 8 + r;
        b_row[np] = row * 64;
        b_sw[np]  = (row >> 1) & 3;
    }

    // output accumulators (4 components) + temp T accumulator
    float aO[4][2][4][4];
#pragma unroll
    for (int b = 0; b < 4; ++b)
#pragma unroll
        for (int mt = 0; mt < 2; ++mt)
#pragma unroll
            for (int nt = 0; nt < 4; ++nt)
#pragma unroll
                for (int e = 0; e < 4; ++e) aO[b][mt][nt][e] = 0.0f;

    auto load_stage = [&](int it) {
        const int z = it >> 3;
        const int s = it & 7;
        const uint32_t sb = sbase + (it & (STAGES - 1)) * STAGE_B;
        const __half* asrc = g_xc + (size_t)z * NT + (size_t)m0 * XN + s * BK + src_off;
        const __half* bsrc = g_wt + (size_t)z * XN * XN + (size_t)n0 * XN + s * BK + src_off;
#pragma unroll
        for (int c = 0; c < 2; ++c) {
            uint32_t da = sb + c * A_CHUNK_B + dst_off;
            CP_ASYNC16(da,        asrc + c * 32);
            CP_ASYNC16(da + 4096, asrc + c * 32 + (size_t)64 * XN);
            CP_ASYNC16(sb + A_OP_B + c * B_CHUNK_B + dst_off, bsrc + c * 32);
        }
    };

    // prologue: 3 stages in flight
    load_stage(0); CP_COMMIT();
    load_stage(1); CP_COMMIT();
    load_stage(2); CP_COMMIT();

#pragma unroll
    for (int z = 0; z < NPROD; ++z) {
        float aT[2][4][4];
#pragma unroll
        for (int mt = 0; mt < 2; ++mt)
#pragma unroll
            for (int nt = 0; nt < 4; ++nt)
#pragma unroll
                for (int e = 0; e < 4; ++e) aT[mt][nt][e] = 0.0f;

#pragma unroll 1
        for (int s = 0; s < 8; ++s) {
            const int it = z * 8 + s;
            CP_WAIT(STAGES - 2);
            __syncthreads();
            if (it + STAGES - 1 < TOTAL_IT) load_stage(it + STAGES - 1);
            CP_COMMIT();

            const uint32_t sb = sbase + (it & (STAGES - 1)) * STAGE_B;
#pragma unroll
            for (int sk = 0; sk < 4; ++sk) {
                const uint32_t abase = sb + (sk >> 1) * A_CHUNK_B;
                const uint32_t bbase = sb + A_OP_B + (sk >> 1) * B_CHUNK_B;
                const uint32_t ca = (uint32_t)(2 * (sk & 1) + a_gbit);
                const uint32_t cb = (uint32_t)(2 * (sk & 1) + b_gbit);
                uint32_t ah[2][4], bh[2][4];
#pragma unroll
                for (int mt = 0; mt < 2; ++mt) {
                    uint32_t off = a_row[mt] + ((ca ^ a_sw[mt]) << 4);
                    ldsm_x4(ah[mt][0], ah[mt][1], ah[mt][2], ah[mt][3], abase + off);
                }
#pragma unroll
                for (int np = 0; np < 2; ++np) {
                    uint32_t off = b_row[np] + ((cb ^ b_sw[np]) << 4);
                    ldsm_x4(bh[np][0], bh[np][1], bh[np][2], bh[np][3], bbase + off);
                }
#pragma unroll
                for (int mt = 0; mt < 2; ++mt) {
#pragma unroll
                    for (int nt = 0; nt < 4; ++nt) {
                        const int np = nt >> 1, sel = (nt & 1) * 2;
                        hmma(aT[mt][nt], ah[mt], bh[np][sel], bh[np][sel + 1]);
                    }
                }
            }
        }

        // fold T_z into output accumulators (signs known at compile time per z)
#pragma unroll
        for (int b = 0; b < 4; ++b) {
            const int sg = SG[z][b];
            if (sg != 0) {
#pragma unroll
                for (int mt = 0; mt < 2; ++mt)
#pragma unroll
                    for (int nt = 0; nt < 4; ++nt)
#pragma unroll
                        for (int e = 0; e < 4; ++e)
                            aO[b][mt][nt][e] += (sg > 0) ? aT[mt][nt][e] : -aT[mt][nt][e];
            }
        }
    }

    // ---- epilogue: interleave 4 components, add bias, float4 stores ----
    const float4* bias4 = reinterpret_cast<const float4*>(bias);
#pragma unroll
    for (int mt = 0; mt < 2; ++mt) {
        int row = m0 + warp_m * 32 + mt * 16 + (lane >> 2);
#pragma unroll
        for (int nt = 0; nt < 4; ++nt) {
            int gnu = n0 + warp_n * 32 + nt * 8 + (lane & 3) * 2;
            float4 bv0 = bias4[gnu];
            float4 bv1 = bias4[gnu + 1];
            float4* o0 = reinterpret_cast<float4*>(out + (size_t)row * OUT_F) + gnu;
            float4* o1 = reinterpret_cast<float4*>(out + (size_t)(row + 8) * OUT_F) + gnu;
            float4 v;
            v.x = aO[0][mt][nt][0] + bv0.x; v.y = aO[1][mt][nt][0] + bv0.y;
            v.z = aO[2][mt][nt][0] + bv0.z; v.w = aO[3][mt][nt][0] + bv0.w;
            o0[0] = v;
            v.x = aO[0][mt][nt][1] + bv1.x; v.y = aO[1][mt][nt][1] + bv1.y;
            v.z = aO[2][mt][nt][1] + bv1.z; v.w = aO[3][mt][nt][1] + bv1.w;
            o0[1] = v;
            v.x = aO[0][mt][nt][2] + bv0.x; v.y = aO[1][mt][nt][2] + bv0.y;
            v.z = aO[2][mt][nt][2] + bv0.z; v.w = aO[3][mt][nt][2] + bv0.w;
            o1[0] = v;
            v.x = aO[0][mt][nt][3] + bv1.x; v.y = aO[1][mt][nt][3] + bv1.y;
            v.z = aO[2][mt][nt][3] + bv1.z; v.w = aO[3][mt][nt][3] + bv1.w;
            o1[1] = v;
        }
    }
}

// ---------------- launch ----------------
extern "C" void kernel_launch(void* const* d_in, const int* in_sizes, int n_in,
                              void* d_out, int out_size) {
    (void)in_sizes; (void)n_in; (void)out_size;
    const float* input  = (const float*)d_in[0];
    const float* weight = (const float*)d_in[1];
    const float* bias   = (const float*)d_in[2];
    float* out = (float*)d_out;

    cudaFuncSetAttribute(qfused_gemm, cudaFuncAttributeMaxDynamicSharedMemorySize, SMEM_TOTAL);

    make_xc_kernel<<<(unsigned)((NT + 255) / 256), 256>>>(input);
    make_wc_kernel<<<dim3(XN / 32, XN / 32), 256>>>(weight);
    qfused_gemm<<<dim3(XN / BNU, N_ROWS / BM), THREADS, SMEM_TOTAL>>>(bias, out);
}

// round 12
// speedup vs baseline: 1.4671x; 1.4671x over previous
#include <cuda_runtime.h>
#include <cuda_fp16.h>
#include <cstdint>

#define N_ROWS 8192
#define IN_F   2048
#define OUT_F  2048
#define XN     512
#define NPROD  8

static constexpr size_t NT = (size_t)N_ROWS * XN;

// ---------------- static device scratch ----------------
__device__ __half g_xc[NPROD * NT];          // 8 X-combos [8192 x 512] fp16 (64 MB)
__device__ __half g_wt[NPROD * XN * XN];     // 8 W-combos [512 x 512] fp16, [nu][kappa]
__device__ __half g_t [NPROD * NT];          // 8 products [8192 x 512] fp16 (64 MB)

// ---------------- prep: X combos (2 elements per thread, half2 stores) ------
__global__ void make_xc_kernel(const float* __restrict__ in) {
    size_t i = (size_t)blockIdx.x * blockDim.x + threadIdx.x;   // pair index
    if (i >= NT / 2) return;
    size_t i2 = i * 2;
    float4 v0 = reinterpret_cast<const float4*>(in)[i2];
    float4 v1 = reinterpret_cast<const float4*>(in)[i2 + 1];
#define PUT(p, e0, e1) \
    *reinterpret_cast<__half2*>(&g_xc[(size_t)(p) * NT + i2]) = __floats2half2_rn(e0, e1)
    PUT(0, v0.x + v0.y, v1.x + v1.y);
    PUT(1, v0.z - v0.w, v1.z - v1.w);
    PUT(2, v0.z + v0.w, v1.z + v1.w);
    PUT(3, v0.x - v0.y, v1.x - v1.y);
    PUT(4, v0.y + v0.z, v1.y + v1.z);
    PUT(5, v0.y - v0.z, v1.y - v1.z);
    PUT(6, v0.x - v0.w, v1.x - v1.w);
    PUT(7, v0.x + v0.w, v1.x + v1.w);
#undef PUT
}

// ---------------- prep: W combos (transposed to [nu][kappa]) ----------------
__global__ void make_wc_kernel(const float* __restrict__ w) {
    __shared__ __half tile[NPROD][32][33];
    const int kap0 = blockIdx.x * 32;
    const int nu0  = blockIdx.y * 32;
    const int tid = threadIdx.x;
    for (int p = 0; p < 4; ++p) {
        int r = p * 8 + (tid >> 5);
        int cnu = tid & 31;
        const float* wr = w + (size_t)(kap0 + r) * OUT_F + nu0 + cnu;
        float b0 = wr[0], b1 = wr[512], b2 = wr[1024], b3 = wr[1536];
        tile[0][r][cnu] = __float2half_rn(b0 - b1);
        tile[1][r][cnu] = __float2half_rn(b2 - b3);
        tile[2][r][cnu] = __float2half_rn(b0 + b1);
        tile[3][r][cnu] = __float2half_rn(b2 + b3);
        tile[4][r][cnu] = __float2half_rn(0.5f * (b1 + b3));
        tile[5][r][cnu] = __float2half_rn(0.5f * (b1 - b3));
        tile[6][r][cnu] = __float2half_rn(0.5f * (b0 - b2));
        tile[7][r][cnu] = __float2half_rn(0.5f * (b0 + b2));
    }
    __syncthreads();
    for (int p = 0; p < 4; ++p) {
        int rnu = p * 8 + (tid >> 5);
        int ck  = tid & 31;
#pragma unroll
        for (int i = 0; i < NPROD; ++i) {
            g_wt[(size_t)i * XN * XN + (size_t)(nu0 + rnu) * XN + kap0 + ck] = tile[i][ck][rnu];
        }
    }
}

// ---------------- PTX helpers ----------------
__device__ __forceinline__ uint32_t smem_u32(const void* p) {
    uint32_t a;
    asm("{ .reg .u64 t; cvta.to.shared.u64 t, %1; cvt.u32.u64 %0, t; }" : "=r"(a) : "l"(p));
    return a;
}

#define CP_ASYNC16(dst, src) \
    asm volatile("cp.async.cg.shared.global [%0], [%1], 16;" :: "r"(dst), "l"(src))
#define CP_COMMIT() asm volatile("cp.async.commit_group;")
#define CP_WAIT(n)  asm volatile("cp.async.wait_group %0;" :: "n"(n))

__device__ __forceinline__ void ldsm_x4(uint32_t& r0, uint32_t& r1, uint32_t& r2, uint32_t& r3,
                                        uint32_t addr) {
    asm volatile("ldmatrix.sync.aligned.m8n8.x4.shared.b16 {%0,%1,%2,%3}, [%4];"
                 : "=r"(r0), "=r"(r1), "=r"(r2), "=r"(r3) : "r"(addr));
}

__device__ __forceinline__ void hmma(float* c, const uint32_t* a, uint32_t b0, uint32_t b1) {
    asm volatile(
        "mma.sync.aligned.m16n8k16.row.col.f32.f16.f16.f32 "
        "{%0,%1,%2,%3}, {%4,%5,%6,%7}, {%8,%9}, {%0,%1,%2,%3};"
        : "+f"(c[0]), "+f"(c[1]), "+f"(c[2]), "+f"(c[3])
        : "r"(a[0]), "r"(a[1]), "r"(a[2]), "r"(a[3]), "r"(b0), "r"(b1));
}

// ---------------- batched GEMM: t_z = XC_z [8192x512] @ WT_z [512x512]^T ----------------
#define BM 128
#define BN 128
#define BK 64
#define STAGES 3
#define THREADS 256
#define KTILES (XN / BK)      // 8

static constexpr int CHUNK_B = BM * 32 * 2;
static constexpr int OP_B    = 2 * CHUNK_B;
static constexpr int STAGE_B = 2 * OP_B;
static constexpr int SMEM_TOTAL = STAGES * STAGE_B;  // 96 KB

__global__ void __launch_bounds__(THREADS, 2) qprod_gemm()
{
    extern __shared__ char smem[];
    const uint32_t sbase = smem_u32(smem);
    const int tid  = threadIdx.x;
    const int wid  = tid >> 5;
    const int lane = tid & 31;
    const int warp_m = wid & 3;
    const int warp_n = wid >> 2;
    const int m0 = blockIdx.y * BM;
    const int n0 = blockIdx.x * BN;
    const int z  = blockIdx.z;

    const __half* gA = g_xc + (size_t)z * NT + (size_t)m0 * XN;
    const __half* gB = g_wt + (size_t)z * XN * XN + (size_t)n0 * XN;
    __half* gT = g_t + (size_t)z * NT;

    const int lr = tid >> 2;
    const int lc = tid & 3;
    const uint32_t dst_off = lr * 64 + ((lc ^ ((lr >> 1) & 3)) << 4);
    const size_t src_off = (size_t)lr * XN + lc * 8;

    const int g = lane >> 3, r = lane & 7;
    uint32_t a_row[2], a_sw[2];
    const int a_gbit = g >> 1;
#pragma unroll
    for (int mt = 0; mt < 2; ++mt) {
        int row = warp_m * 32 + mt * 16 + (g & 1) * 8 + r;
        a_row[mt] = row * 64;
        a_sw[mt]  = (row >> 1) & 3;
    }
    uint32_t b_row[4], b_sw[4];
    const int b_gbit = g & 1;
#pragma unroll
    for (int np = 0; np < 4; ++np) {
        int row = warp_n * 64 + np * 16 + (g >> 1) * 8 + r;
        b_row[np] = row * 64;
        b_sw[np]  = (row >> 1) & 3;
    }

    float acc[2][8][4];
#pragma unroll
    for (int mt = 0; mt < 2; ++mt)
#pragma unroll
        for (int nt = 0; nt < 8; ++nt)
#pragma unroll
            for (int e = 0; e < 4; ++e) acc[mt][nt][e] = 0.0f;

    int slot_of[KTILES + STAGES];
#pragma unroll
    for (int s = 0; s < KTILES + STAGES; ++s) slot_of[s] = s % STAGES;

    auto load_stage = [&](int s) {
        const int kc = s * BK;
        const uint32_t sb = sbase + slot_of[s] * STAGE_B;
        {
            const __half* asrc = gA + kc + src_off;
            const __half* bsrc = gB + kc + src_off;
#pragma unroll
            for (int c = 0; c < 2; ++c) {
                uint32_t da = sb + c * CHUNK_B + dst_off;
                uint32_t db = sb + OP_B + c * CHUNK_B + dst_off;
                CP_ASYNC16(da,        asrc + c * 32);
                CP_ASYNC16(da + 4096, asrc + c * 32 + (size_t)64 * XN);
                CP_ASYNC16(db,        bsrc + c * 32);
                CP_ASYNC16(db + 4096, bsrc + c * 32 + (size_t)64 * XN);
            }
        }
    };

    load_stage(0); CP_COMMIT();
    load_stage(1); CP_COMMIT();

    for (int s = 0; s < KTILES; ++s) {
        CP_WAIT(1);
        __syncthreads();
        if (s + 2 < KTILES) load_stage(s + 2);
        CP_COMMIT();

        const uint32_t sb = sbase + slot_of[s] * STAGE_B;
#pragma unroll
        for (int sk = 0; sk < 4; ++sk) {
            const uint32_t abase = sb + (sk >> 1) * CHUNK_B;
            const uint32_t bbase = sb + OP_B + (sk >> 1) * CHUNK_B;
            const uint32_t ca = (uint32_t)(2 * (sk & 1) + a_gbit);
            const uint32_t cb = (uint32_t)(2 * (sk & 1) + b_gbit);
            uint32_t ah[2][4], bh[4][4];
#pragma unroll
            for (int mt = 0; mt < 2; ++mt) {
                uint32_t off = a_row[mt] + ((ca ^ a_sw[mt]) << 4);
                ldsm_x4(ah[mt][0], ah[mt][1], ah[mt][2], ah[mt][3], abase + off);
            }
#pragma unroll
            for (int np = 0; np < 4; ++np) {
                uint32_t off = b_row[np] + ((cb ^ b_sw[np]) << 4);
                ldsm_x4(bh[np][0], bh[np][1], bh[np][2], bh[np][3], bbase + off);
            }
#pragma unroll
            for (int mt = 0; mt < 2; ++mt) {
#pragma unroll
                for (int nt = 0; nt < 8; ++nt) {
                    const int np = nt >> 1, sel = (nt & 1) * 2;
                    hmma(acc[mt][nt], ah[mt], bh[np][sel], bh[np][sel + 1]);
                }
            }
        }
    }

    // ---- epilogue: store t (fp16, pitch 512) ----
#pragma unroll
    for (int mt = 0; mt < 2; ++mt) {
        int row = m0 + warp_m * 32 + mt * 16 + (lane >> 2);
#pragma unroll
        for (int nt = 0; nt < 8; ++nt) {
            int col = n0 + warp_n * 64 + nt * 8 + (lane & 3) * 2;
            *reinterpret_cast<__half2*>(gT + (size_t)row * XN + col) =
                __floats2half2_rn(acc[mt][nt][0], acc[mt][nt][1]);
            *reinterpret_cast<__half2*>(gT + (size_t)(row + 8) * XN + col) =
                __floats2half2_rn(acc[mt][nt][2], acc[mt][nt][3]);
        }
    }
}

// ---------------- combine: O from 8 fp16 products + bias (2 elems/thread) ----
// O0 = T1 + (T4+T5) + (T6+T7)
// O1 = T0 + (T4+T5) - (T6+T7)
// O2 = T2 - (T4-T5) + (T6-T7)
// O3 = -T3 - (T4-T5) - (T6-T7)
__global__ void combine_kernel(const float* __restrict__ bias, float* __restrict__ out) {
    size_t i = (size_t)blockIdx.x * blockDim.x + threadIdx.x;   // pair index
    if (i >= NT / 2) return;
    size_t i2 = i * 2;
    float2 T[8];
#pragma unroll
    for (int p = 0; p < 8; ++p) {
        __half2 h = *reinterpret_cast<const __half2*>(&g_t[(size_t)p * NT + i2]);
        T[p] = __half22float2(h);
    }
    int nu = (int)(i2 & 511);
    const float4* bias4 = reinterpret_cast<const float4*>(bias);
    float4* out4 = reinterpret_cast<float4*>(out);
#pragma unroll
    for (int j = 0; j < 2; ++j) {
        float t0 = (j ? T[0].y : T[0].x), t1 = (j ? T[1].y : T[1].x);
        float t2 = (j ? T[2].y : T[2].x), t3 = (j ? T[3].y : T[3].x);
        float t4 = (j ? T[4].y : T[4].x), t5 = (j ? T[5].y : T[5].x);
        float t6 = (j ? T[6].y : T[6].x), t7 = (j ? T[7].y : T[7].x);
        float s1 = t4 + t5, s2 = t6 + t7;
        float d1 = t4 - t5, d2 = t6 - t7;
        float4 b = bias4[nu + j];
        float4 o;
        o.x =  t1 + s1 + s2 + b.x;
        o.y =  t0 + s1 - s2 + b.y;
        o.z =  t2 - d1 + d2 + b.z;
        o.w = -t3 - d1 - d2 + b.w;
        out4[i2 + j] = o;
    }
}

// ---------------- launch ----------------
extern "C" void kernel_launch(void* const* d_in, const int* in_sizes, int n_in,
                              void* d_out, int out_size) {
    (void)in_sizes; (void)n_in; (void)out_size;
    const float* input  = (const float*)d_in[0];
    const float* weight = (const float*)d_in[1];
    const float* bias   = (const float*)d_in[2];
    float* out = (float*)d_out;

    cudaFuncSetAttribute(qprod_gemm, cudaFuncAttributeMaxDynamicSharedMemorySize, SMEM_TOTAL);

    make_xc_kernel<<<(unsigned)((NT / 2 + 255) / 256), 256>>>(input);
    make_wc_kernel<<<dim3(XN / 32, XN / 32), 256>>>(weight);
    qprod_gemm<<<dim3(XN / BN, N_ROWS / BM, NPROD), THREADS, SMEM_TOTAL>>>();
    combine_kernel<<<(unsigned)((NT / 2 + 255) / 256), 256>>>(bias, out);
}